// round 1
// baseline (speedup 1.0000x reference)
#include <cuda_runtime.h>
#include <math.h>

#define B_   128
#define N_   256
#define E_   2048
#define GTOT 256   // q graphs [0,128) + c graphs [128,256)

// ---------------- device scratch (static globals: no allocs) ----------------
__device__ float    g_bufA[GTOT * N_ * 128];   // 33.5 MB ping
__device__ float    g_bufB[GTOT * N_ * 128];   // 33.5 MB pong
__device__ int      g_srcs[GTOT * E_];
__device__ float    g_coef[GTOT * E_];
__device__ int      g_rowptr[GTOT * 257];
__device__ float    g_invdeg[GTOT * N_];
__device__ float    g_pool[GTOT * 32];
__device__ float    g_scoresT[B_ * 16];
__device__ unsigned g_minmax[2];
__device__ int      g_hist[16];

// monotone float<->uint mapping for atomicMin/Max over signed floats
__device__ __forceinline__ unsigned encf(float f) {
    unsigned u = __float_as_uint(f);
    return (u & 0x80000000u) ? ~u : (u | 0x80000000u);
}
__device__ __forceinline__ float decf(unsigned u) {
    return (u & 0x80000000u) ? __uint_as_float(u & 0x7fffffffu)
                             : __uint_as_float(~u);
}

// ---------------- init ----------------
__global__ void k_init() {
    if (threadIdx.x == 0) { g_minmax[0] = 0xffffffffu; g_minmax[1] = 0u; }
    if (threadIdx.x < 16) g_hist[threadIdx.x] = 0;
}

// ---------------- CSR build (per graph): deg, dinv, rowptr, dst-sorted src+coef ----------------
__global__ void __launch_bounds__(256) k_csr(const int* __restrict__ eq,
                                             const int* __restrict__ ec) {
    const int g = blockIdx.x;
    const int* base = (g < B_) ? (eq + (size_t)g * 2 * E_)
                               : (ec + (size_t)(g - B_) * 2 * E_);
    const int* src = base;
    const int* dst = base + E_;

    __shared__ int   cnt[256];
    __shared__ int   scan[256];
    __shared__ int   off[256];
    __shared__ float dinv[256];

    const int t = threadIdx.x;
    cnt[t] = 0;
    __syncthreads();
    for (int e = t; e < E_; e += 256) atomicAdd(&cnt[dst[e]], 1);
    __syncthreads();

    float deg = (float)cnt[t] + 1.0f;
    dinv[t] = rsqrtf(deg);
    g_invdeg[g * N_ + t] = 1.0f / deg;

    int v = cnt[t];
    scan[t] = v;
    __syncthreads();
    for (int s = 1; s < 256; s <<= 1) {
        int add = (t >= s) ? scan[t - s] : 0;
        __syncthreads();
        scan[t] += add;
        __syncthreads();
    }
    int excl = scan[t] - v;
    off[t] = excl;
    g_rowptr[g * 257 + t] = excl;
    if (t == 0) g_rowptr[g * 257 + 256] = E_;
    __syncthreads();

    for (int e = t; e < E_; e += 256) {
        int d = dst[e];
        int s_ = src[e];
        int pos = atomicAdd(&off[d], 1);
        g_srcs[g * E_ + pos] = s_;
        g_coef[g * E_ + pos] = dinv[s_] * dinv[d];
    }
}

// ---------------- batched GEMM: H[g] = X[g] @ W, W resident in smem ----------------
// block = 256 thr, BM = 64 rows/tile, grid = (4, 256 graphs)
template<int K, int FO, bool L1>
__global__ void __launch_bounds__(256) k_gemm(const float* __restrict__ inA,
                                              const float* __restrict__ inB,
                                              const float* __restrict__ W,
                                              float* __restrict__ out) {
    constexpr int TN = FO / 32;
    extern __shared__ float sm[];
    float* Ws = sm;              // K*FO
    float* Xs = sm + K * FO;     // 64*K

    const int g  = blockIdx.y;
    const int rt = blockIdx.x;
    const float* X;
    if constexpr (L1)
        X = (g < B_) ? (inA + (size_t)g * N_ * K)
                     : (inB + (size_t)(g - B_) * N_ * K);
    else
        X = inA + (size_t)g * N_ * K;
    X += (size_t)rt * 64 * K;

    const int t = threadIdx.x;
    for (int i = t; i < K * FO / 4; i += 256)
        ((float4*)Ws)[i] = ((const float4*)W)[i];
    for (int i = t; i < 64 * K / 4; i += 256)
        ((float4*)Xs)[i] = ((const float4*)X)[i];
    __syncthreads();

    const int ty = t >> 5;   // warp id -> 8 contiguous rows
    const int tx = t & 31;   // lane -> TN cols
    const float* xrow = Xs + ty * 8 * K;

    float acc[8][TN];
#pragma unroll
    for (int m = 0; m < 8; m++)
#pragma unroll
        for (int j = 0; j < TN; j++) acc[m][j] = 0.f;

    for (int k = 0; k < K; k += 4) {
        float4 xv[8];
#pragma unroll
        for (int m = 0; m < 8; m++)
            xv[m] = *(const float4*)(xrow + m * K + k);
#pragma unroll
        for (int kk = 0; kk < 4; kk++) {
            float wv[TN];
            if constexpr (TN == 4) {
                float4 w = *(const float4*)(Ws + (k + kk) * FO + tx * 4);
                wv[0] = w.x; wv[1] = w.y; wv[2] = w.z; wv[3] = w.w;
            } else if constexpr (TN == 2) {
                float2 w = *(const float2*)(Ws + (k + kk) * FO + tx * 2);
                wv[0] = w.x; wv[1] = w.y;
            } else {
                wv[0] = Ws[(k + kk) * FO + tx];
            }
#pragma unroll
            for (int m = 0; m < 8; m++) {
                float xm = ((const float*)&xv[m])[kk];
#pragma unroll
                for (int j = 0; j < TN; j++) acc[m][j] += xm * wv[j];
            }
        }
    }

    float* O = out + (size_t)g * N_ * FO + (size_t)(rt * 64 + ty * 8) * FO + tx * TN;
#pragma unroll
    for (int m = 0; m < 8; m++) {
        if constexpr (TN == 4) {
            float4 v = make_float4(acc[m][0], acc[m][1], acc[m][2], acc[m][3]);
            *(float4*)(O + m * FO) = v;
        } else if constexpr (TN == 2) {
            float2 v = make_float2(acc[m][0], acc[m][1]);
            *(float2*)(O + m * FO) = v;
        } else {
            O[m * FO] = acc[m][0];
        }
    }
}

// ---------------- GCN aggregate: out = agg + h/deg + b (opt relu), smem gather ----------------
template<int FD, bool RELU>
__global__ void __launch_bounds__(512) k_agg(const float* __restrict__ H,
                                             const float* __restrict__ bias,
                                             float* __restrict__ out) {
    extern __shared__ float sm[];
    float* hsm = sm;                        // N_*FD
    int*   ssm = (int*)(sm + N_ * FD);      // E_
    float* csm = (float*)(ssm + E_);        // E_
    int*   rsm = (int*)(csm + E_);          // 257

    const int g = blockIdx.x;
    const int t = threadIdx.x;

    const float4* Hg = (const float4*)(H + (size_t)g * N_ * FD);
    float4* h4 = (float4*)hsm;
    for (int i = t; i < N_ * FD / 4; i += 512) h4[i] = Hg[i];
    for (int i = t; i < E_; i += 512) {
        ssm[i] = g_srcs[g * E_ + i];
        csm[i] = g_coef[g * E_ + i];
    }
    for (int i = t; i < 257; i += 512) rsm[i] = g_rowptr[g * 257 + i];
    __syncthreads();

    const int f = t % FD;
    const float bf = bias[f];
    for (int n = t / FD; n < N_; n += 512 / FD) {
        int e0 = rsm[n], e1 = rsm[n + 1];
        float a0 = 0.f, a1 = 0.f;
        int e = e0;
        for (; e + 1 < e1; e += 2) {
            a0 += hsm[ssm[e] * FD + f] * csm[e];
            a1 += hsm[ssm[e + 1] * FD + f] * csm[e + 1];
        }
        if (e < e1) a0 += hsm[ssm[e] * FD + f] * csm[e];
        float v = a0 + a1 + hsm[n * FD + f] * g_invdeg[g * N_ + n] + bf;
        if (RELU) v = fmaxf(v, 0.f);
        out[(size_t)g * N_ * FD + (size_t)n * FD + f] = v;
    }
}

// ---------------- SimGNN attention pooling (f3 = 32) ----------------
__global__ void __launch_bounds__(256) k_pool(const float* __restrict__ emb,
                                              const float* __restrict__ Watt) {
    __shared__ float xs[N_ * 33];   // padded rows: conflict-free row reads
    __shared__ float colsum[32];
    __shared__ float ctx[32];
    __shared__ float score[N_];

    const int g = blockIdx.x, t = threadIdx.x;
    const float* X = emb + (size_t)g * N_ * 32;
    for (int i = t; i < N_ * 32; i += 256)
        xs[(i >> 5) * 33 + (i & 31)] = X[i];
    __syncthreads();

    if (t < 32) {
        float s = 0.f;
        for (int n = 0; n < N_; n++) s += xs[n * 33 + t];
        colsum[t] = s;
    }
    __syncthreads();
    if (t < 32) {
        float a = 0.f;
        for (int i = 0; i < 32; i++) a += colsum[i] * Watt[t * 32 + i];
        ctx[t] = tanhf(a * (1.0f / 256.0f));
    }
    __syncthreads();
    {
        float d = 0.f;
#pragma unroll
        for (int i = 0; i < 32; i++) d += xs[t * 33 + i] * ctx[i];
        score[t] = 1.0f / (1.0f + expf(-d));
    }
    __syncthreads();
    if (t < 32) {
        float s = 0.f;
        for (int n = 0; n < N_; n++) s += xs[n * 33 + t] * score[n];
        g_pool[g * 32 + t] = s;
    }
}

// ---------------- NTN: relu(e1^T W_t e2 + V_t . [e1;e2] + b_t) ----------------
__global__ void __launch_bounds__(512) k_ntn(const float* __restrict__ ntnW,
                                             const float* __restrict__ ntnV,
                                             const float* __restrict__ ntnb) {
    const int b = blockIdx.x;
    __shared__ float e1[32], e2[32];
    const int t = threadIdx.x;
    if (t < 32)      e1[t]      = g_pool[b * 32 + t];
    else if (t < 64) e2[t - 32] = g_pool[(B_ + b) * 32 + (t - 32)];
    __syncthreads();

    const int w = t >> 5, lane = t & 31;   // w = tensor neuron
    const float* Wt = ntnW + w * 1024;
    float a = 0.f;
#pragma unroll 8
    for (int j = 0; j < 32; j++) a += Wt[lane * 32 + j] * e2[j];
    float partial = e1[lane] * a
                  + e1[lane] * ntnV[w * 64 + lane]
                  + e2[lane] * ntnV[w * 64 + 32 + lane];
#pragma unroll
    for (int o = 16; o; o >>= 1)
        partial += __shfl_xor_sync(0xffffffffu, partial, o);
    if (lane == 0)
        g_scoresT[b * 16 + w] = fmaxf(partial + ntnb[w], 0.f);
}

// ---------------- pairwise dot s[b,n,m] = q_n . c_m, plus global min/max ----------------
__global__ void __launch_bounds__(256) k_pair(const float* __restrict__ emb,
                                              float* __restrict__ s) {
    __shared__ float qs[64 * 32];
    __shared__ float cs[256 * 33];
    __shared__ float wmn[8], wmx[8];

    const int b = blockIdx.y, nt = blockIdx.x;
    const int t = threadIdx.x;
    const float* Q = emb + (size_t)b * N_ * 32 + (size_t)nt * 64 * 32;
    const float* C = emb + (size_t)(B_ + b) * N_ * 32;
    for (int i = t; i < 64 * 32; i += 256) qs[i] = Q[i];
    for (int i = t; i < 256 * 32; i += 256)
        cs[(i >> 5) * 33 + (i & 31)] = C[i];
    __syncthreads();

    float cr[32];
#pragma unroll
    for (int k = 0; k < 32; k++) cr[k] = cs[t * 33 + k];

    float vmin = 3.402823466e38f, vmax = -3.402823466e38f;
    float* Sb = s + (size_t)b * N_ * N_ + (size_t)nt * 64 * N_;
    for (int n = 0; n < 64; n += 4) {
        float a0 = 0.f, a1 = 0.f, a2 = 0.f, a3 = 0.f;
#pragma unroll
        for (int k = 0; k < 32; k++) {
            float cv = cr[k];
            a0 += qs[(n + 0) * 32 + k] * cv;
            a1 += qs[(n + 1) * 32 + k] * cv;
            a2 += qs[(n + 2) * 32 + k] * cv;
            a3 += qs[(n + 3) * 32 + k] * cv;
        }
        Sb[(n + 0) * N_ + t] = a0;
        Sb[(n + 1) * N_ + t] = a1;
        Sb[(n + 2) * N_ + t] = a2;
        Sb[(n + 3) * N_ + t] = a3;
        vmin = fminf(fminf(vmin, a0), fminf(fminf(a1, a2), a3));
        vmax = fmaxf(fmaxf(vmax, a0), fmaxf(fmaxf(a1, a2), a3));
    }
#pragma unroll
    for (int o = 16; o; o >>= 1) {
        vmin = fminf(vmin, __shfl_xor_sync(0xffffffffu, vmin, o));
        vmax = fmaxf(vmax, __shfl_xor_sync(0xffffffffu, vmax, o));
    }
    if ((t & 31) == 0) { wmn[t >> 5] = vmin; wmx[t >> 5] = vmax; }
    __syncthreads();
    if (t == 0) {
        float m = wmn[0], M = wmx[0];
        for (int i = 1; i < 8; i++) { m = fminf(m, wmn[i]); M = fmaxf(M, wmx[i]); }
        atomicMin(&g_minmax[0], encf(m));
        atomicMax(&g_minmax[1], encf(M));
    }
}

// ---------------- histogram over 8.4M values, ballot counting ----------------
__global__ void __launch_bounds__(256) k_hist(const float* __restrict__ s) {
    __shared__ int hsm[16];
    const int t = threadIdx.x;
    if (t < 16) hsm[t] = 0;
    __syncthreads();

    const float lo = decf(g_minmax[0]);
    const float hi = decf(g_minmax[1]);
    const float range = hi - lo;
    const int lane = t & 31;
    int cnt = 0;   // lane i accumulates bin i (lanes 16..31 idle)

    size_t idx0 = (size_t)blockIdx.x * 256 + t;
    for (int it = 0; it < 32; it++) {                 // 1024*256*32 == 8388608 exactly
        float v = s[idx0 + (size_t)it * 262144];
        int bi = (int)floorf((v - lo) / range * 16.0f);
        bi = bi < 0 ? 0 : (bi > 15 ? 15 : bi);
#pragma unroll
        for (int b = 0; b < 16; b++) {
            unsigned m = __ballot_sync(0xffffffffu, bi == b);
            if (lane == b) cnt += __popc(m);
        }
    }
    if (lane < 16) atomicAdd(&hsm[lane], cnt);
    __syncthreads();
    if (t < 16) atomicAdd(&g_hist[t], hsm[t]);
}

// ---------------- final MLP head ----------------
__global__ void k_final(const float* __restrict__ fc1W, const float* __restrict__ fc1b,
                        const float* __restrict__ fc2W, const float* __restrict__ fc2b,
                        float* __restrict__ out) {
    __shared__ float h[16];
    const int b = threadIdx.x;
    if (b < 16) h[b] = (float)g_hist[b] * (1.0f / 8388608.0f);
    __syncthreads();

    float sc[16];
#pragma unroll
    for (int t = 0; t < 16; t++) sc[t] = g_scoresT[b * 16 + t];

    float p = fc2b[0];
#pragma unroll
    for (int j = 0; j < 16; j++) {
        float a = fc1b[j];
#pragma unroll
        for (int t = 0; t < 16; t++) a += sc[t] * fc1W[j * 32 + t];
#pragma unroll
        for (int k = 0; k < 16; k++) a += h[k] * fc1W[j * 32 + 16 + k];
        p += fmaxf(a, 0.f) * fc2W[j];
    }
    out[b] = 1.0f / (1.0f + expf(-p));
}

// ---------------- launch ----------------
extern "C" void kernel_launch(void* const* d_in, const int* in_sizes, int n_in,
                              void* d_out, int out_size) {
    const float* xq   = (const float*)d_in[0];
    const float* xc   = (const float*)d_in[1];
    const int*   eq   = (const int*)d_in[2];
    const int*   ec   = (const int*)d_in[3];
    const float* W1   = (const float*)d_in[4];
    const float* b1   = (const float*)d_in[5];
    const float* W2   = (const float*)d_in[6];
    const float* b2   = (const float*)d_in[7];
    const float* W3   = (const float*)d_in[8];
    const float* b3   = (const float*)d_in[9];
    const float* Watt = (const float*)d_in[10];
    const float* ntnW = (const float*)d_in[11];
    const float* ntnV = (const float*)d_in[12];
    const float* ntnb = (const float*)d_in[13];
    const float* fc1W = (const float*)d_in[14];
    const float* fc1b = (const float*)d_in[15];
    const float* fc2W = (const float*)d_in[16];
    const float* fc2b = (const float*)d_in[17];
    float* out = (float*)d_out;

    float *bufA, *bufB;
    cudaGetSymbolAddress((void**)&bufA, g_bufA);
    cudaGetSymbolAddress((void**)&bufB, g_bufB);

    constexpr int SM_G1 = (128 * 128 + 64 * 128) * 4;   // 96 KB
    constexpr int SM_G2 = (128 * 64  + 64 * 128) * 4;   // 64 KB
    constexpr int SM_G3 = (64 * 32   + 64 * 64)  * 4;   // 24 KB
    constexpr int SM_A1 = (N_ * 128 + 2 * E_ + 264) * 4; // ~145 KB
    constexpr int SM_A2 = (N_ * 64  + 2 * E_ + 264) * 4; // ~81 KB
    constexpr int SM_A3 = (N_ * 32  + 2 * E_ + 264) * 4; // ~49 KB

    cudaFuncSetAttribute(k_gemm<128, 128, true>,  cudaFuncAttributeMaxDynamicSharedMemorySize, SM_G1);
    cudaFuncSetAttribute(k_gemm<128, 64,  false>, cudaFuncAttributeMaxDynamicSharedMemorySize, SM_G2);
    cudaFuncSetAttribute(k_gemm<64,  32,  false>, cudaFuncAttributeMaxDynamicSharedMemorySize, SM_G3);
    cudaFuncSetAttribute(k_agg<128, true>,  cudaFuncAttributeMaxDynamicSharedMemorySize, SM_A1);
    cudaFuncSetAttribute(k_agg<64,  true>,  cudaFuncAttributeMaxDynamicSharedMemorySize, SM_A2);
    cudaFuncSetAttribute(k_agg<32,  false>, cudaFuncAttributeMaxDynamicSharedMemorySize, SM_A3);

    k_init<<<1, 32>>>();
    k_csr<<<GTOT, 256>>>(eq, ec);

    k_gemm<128, 128, true><<<dim3(4, GTOT), 256, SM_G1>>>(xq, xc, W1, bufA);
    k_agg<128, true><<<GTOT, 512, SM_A1>>>(bufA, b1, bufB);

    k_gemm<128, 64, false><<<dim3(4, GTOT), 256, SM_G2>>>(bufB, bufB, W2, bufA);
    k_agg<64, true><<<GTOT, 512, SM_A2>>>(bufA, b2, bufB);

    k_gemm<64, 32, false><<<dim3(4, GTOT), 256, SM_G3>>>(bufB, bufB, W3, bufA);
    k_agg<32, false><<<GTOT, 512, SM_A3>>>(bufA, b3, bufB);   // bufB = final node embeddings

    k_pool<<<GTOT, 256>>>(bufB, Watt);
    k_ntn<<<B_, 512>>>(ntnW, ntnV, ntnb);

    k_pair<<<dim3(4, B_), 256>>>(bufB, bufA);   // bufA reused as s [128,256,256]
    k_hist<<<1024, 256>>>(bufA);

    k_final<<<1, B_>>>(fc1W, fc1b, fc2W, fc2b, out);
}

// round 2
// speedup vs baseline: 1.2330x; 1.2330x over previous
#include <cuda_runtime.h>
#include <math.h>

#define B_   128
#define N_   256
#define E_   2048
#define GTOT 256   // q graphs [0,128) + c graphs [128,256)

// ---------------- device scratch (static globals: no allocs) ----------------
__device__ float    g_bufA[GTOT * N_ * 128];   // 33.5 MB ping (also reused as s)
__device__ float    g_bufB[GTOT * N_ * 128];   // 33.5 MB pong
__device__ float2   g_edge[GTOT * E_];         // packed (coef, src-as-float-bits)
__device__ int      g_rowptr[GTOT * 257];
__device__ float    g_invdeg[GTOT * N_];
__device__ float    g_pool[GTOT * 32];
__device__ float    g_scoresT[B_ * 16];
__device__ unsigned g_minmax[2];
__device__ int      g_hist[16];

// monotone float<->uint mapping for atomicMin/Max over signed floats
__device__ __forceinline__ unsigned encf(float f) {
    unsigned u = __float_as_uint(f);
    return (u & 0x80000000u) ? ~u : (u | 0x80000000u);
}
__device__ __forceinline__ float decf(unsigned u) {
    return (u & 0x80000000u) ? __uint_as_float(u & 0x7fffffffu)
                             : __uint_as_float(~u);
}

// ---------------- CSR build (per graph) + global init in block 0 ----------------
__global__ void __launch_bounds__(256) k_csr(const int* __restrict__ eq,
                                             const int* __restrict__ ec) {
    const int g = blockIdx.x;
    const int t = threadIdx.x;
    if (g == 0) {
        if (t == 0) { g_minmax[0] = 0xffffffffu; g_minmax[1] = 0u; }
        if (t < 16) g_hist[t] = 0;
    }
    const int* base = (g < B_) ? (eq + (size_t)g * 2 * E_)
                               : (ec + (size_t)(g - B_) * 2 * E_);
    const int* src = base;
    const int* dst = base + E_;

    __shared__ int   cnt[256];
    __shared__ int   scan[256];
    __shared__ int   off[256];
    __shared__ float dinv[256];

    cnt[t] = 0;
    __syncthreads();
    for (int e = t; e < E_; e += 256) atomicAdd(&cnt[dst[e]], 1);
    __syncthreads();

    float deg = (float)cnt[t] + 1.0f;
    dinv[t] = rsqrtf(deg);
    g_invdeg[g * N_ + t] = 1.0f / deg;

    int v = cnt[t];
    scan[t] = v;
    __syncthreads();
    for (int s = 1; s < 256; s <<= 1) {
        int add = (t >= s) ? scan[t - s] : 0;
        __syncthreads();
        scan[t] += add;
        __syncthreads();
    }
    int excl = scan[t] - v;
    off[t] = excl;
    g_rowptr[g * 257 + t] = excl;
    if (t == 0) g_rowptr[g * 257 + 256] = E_;
    __syncthreads();

    for (int e = t; e < E_; e += 256) {
        int d = dst[e];
        int s_ = src[e];
        int pos = atomicAdd(&off[d], 1);
        g_edge[g * E_ + pos] = make_float2(dinv[s_] * dinv[d], __int_as_float(s_));
    }
}

// ---------------- batched GEMM: H[g] = X[g] @ W, W resident in smem ----------------
// block = 256 thr, BM = 64 rows/tile, grid = (4, 256 graphs)
template<int K, int FO, bool L1>
__global__ void __launch_bounds__(256) k_gemm(const float* __restrict__ inA,
                                              const float* __restrict__ inB,
                                              const float* __restrict__ W,
                                              float* __restrict__ out) {
    constexpr int TN = FO / 32;
    extern __shared__ float sm[];
    float* Ws = sm;              // K*FO
    float* Xs = sm + K * FO;     // 64*K

    const int g  = blockIdx.y;
    const int rt = blockIdx.x;
    const float* X;
    if constexpr (L1)
        X = (g < B_) ? (inA + (size_t)g * N_ * K)
                     : (inB + (size_t)(g - B_) * N_ * K);
    else
        X = inA + (size_t)g * N_ * K;
    X += (size_t)rt * 64 * K;

    const int t = threadIdx.x;
    for (int i = t; i < K * FO / 4; i += 256)
        ((float4*)Ws)[i] = ((const float4*)W)[i];
    for (int i = t; i < 64 * K / 4; i += 256)
        ((float4*)Xs)[i] = ((const float4*)X)[i];
    __syncthreads();

    const int ty = t >> 5;   // warp id -> 8 contiguous rows
    const int tx = t & 31;   // lane -> TN cols
    const float* xrow = Xs + ty * 8 * K;

    float acc[8][TN];
#pragma unroll
    for (int m = 0; m < 8; m++)
#pragma unroll
        for (int j = 0; j < TN; j++) acc[m][j] = 0.f;

    for (int k = 0; k < K; k += 4) {
        float4 xv[8];
#pragma unroll
        for (int m = 0; m < 8; m++)
            xv[m] = *(const float4*)(xrow + m * K + k);
#pragma unroll
        for (int kk = 0; kk < 4; kk++) {
            float wv[TN];
            if constexpr (TN == 4) {
                float4 w = *(const float4*)(Ws + (k + kk) * FO + tx * 4);
                wv[0] = w.x; wv[1] = w.y; wv[2] = w.z; wv[3] = w.w;
            } else if constexpr (TN == 2) {
                float2 w = *(const float2*)(Ws + (k + kk) * FO + tx * 2);
                wv[0] = w.x; wv[1] = w.y;
            } else {
                wv[0] = Ws[(k + kk) * FO + tx];
            }
#pragma unroll
            for (int m = 0; m < 8; m++) {
                float xm = ((const float*)&xv[m])[kk];
#pragma unroll
                for (int j = 0; j < TN; j++) acc[m][j] += xm * wv[j];
            }
        }
    }

    float* O = out + (size_t)g * N_ * FO + (size_t)(rt * 64 + ty * 8) * FO + tx * TN;
#pragma unroll
    for (int m = 0; m < 8; m++) {
        if constexpr (TN == 4) {
            float4 v = make_float4(acc[m][0], acc[m][1], acc[m][2], acc[m][3]);
            *(float4*)(O + m * FO) = v;
        } else if constexpr (TN == 2) {
            float2 v = make_float2(acc[m][0], acc[m][1]);
            *(float2*)(O + m * FO) = v;
        } else {
            O[m * FO] = acc[m][0];
        }
    }
}

// ---------------- GCN aggregate (float4-vectorized): out = agg + h/deg + b ----------------
// Each thread owns one float4 feature-quad of one node; per edge: one LDS.64
// of packed (coef,src) + one LDS.128 gather + 4 FFMA.
template<int FD, bool RELU>
__global__ void __launch_bounds__(1024) k_agg(const float* __restrict__ H,
                                              const float* __restrict__ bias,
                                              float* __restrict__ out) {
    constexpr int QPN = FD / 4;          // feature quads per node
    constexpr int NPB = 1024 / QPN;      // nodes processed concurrently
    extern __shared__ float sm[];
    float4* hsm = (float4*)sm;                       // N_*QPN float4
    float2* esm = (float2*)(sm + N_ * FD);           // E_ float2
    int*    rsm = (int*)(sm + N_ * FD + 2 * E_);     // 257

    const int g = blockIdx.x;
    const int t = threadIdx.x;

    const float4* Hg = (const float4*)(H + (size_t)g * N_ * FD);
    for (int i = t; i < N_ * QPN; i += 1024) hsm[i] = Hg[i];
    {
        const float2* Eg = g_edge + (size_t)g * E_;
        for (int i = t; i < E_; i += 1024) esm[i] = Eg[i];
    }
    for (int i = t; i < 257; i += 1024) rsm[i] = g_rowptr[g * 257 + i];
    __syncthreads();

    const int fq = t % QPN;
    const int n0 = t / QPN;
    const float4 bf = ((const float4*)bias)[fq];
    float4* O = (float4*)(out + (size_t)g * N_ * FD);

#pragma unroll
    for (int n = n0; n < N_; n += NPB) {
        const int e0 = rsm[n], e1 = rsm[n + 1];
        float4 a0 = make_float4(0.f, 0.f, 0.f, 0.f);
        float4 a1 = make_float4(0.f, 0.f, 0.f, 0.f);
        int e = e0;
        for (; e + 1 < e1; e += 2) {
            float2 ed0 = esm[e];
            float2 ed1 = esm[e + 1];
            float4 h0 = hsm[__float_as_int(ed0.y) * QPN + fq];
            float4 h1 = hsm[__float_as_int(ed1.y) * QPN + fq];
            a0.x += h0.x * ed0.x; a0.y += h0.y * ed0.x;
            a0.z += h0.z * ed0.x; a0.w += h0.w * ed0.x;
            a1.x += h1.x * ed1.x; a1.y += h1.y * ed1.x;
            a1.z += h1.z * ed1.x; a1.w += h1.w * ed1.x;
        }
        if (e < e1) {
            float2 ed0 = esm[e];
            float4 h0 = hsm[__float_as_int(ed0.y) * QPN + fq];
            a0.x += h0.x * ed0.x; a0.y += h0.y * ed0.x;
            a0.z += h0.z * ed0.x; a0.w += h0.w * ed0.x;
        }
        const float id = g_invdeg[g * N_ + n];
        float4 hs = hsm[n * QPN + fq];
        float4 v;
        v.x = a0.x + a1.x + hs.x * id + bf.x;
        v.y = a0.y + a1.y + hs.y * id + bf.y;
        v.z = a0.z + a1.z + hs.z * id + bf.z;
        v.w = a0.w + a1.w + hs.w * id + bf.w;
        if (RELU) {
            v.x = fmaxf(v.x, 0.f); v.y = fmaxf(v.y, 0.f);
            v.z = fmaxf(v.z, 0.f); v.w = fmaxf(v.w, 0.f);
        }
        O[n * QPN + fq] = v;
    }
}

// ---------------- SimGNN attention pooling (f3 = 32) ----------------
__global__ void __launch_bounds__(256) k_pool(const float* __restrict__ emb,
                                              const float* __restrict__ Watt) {
    __shared__ float xs[N_ * 33];   // padded rows: conflict-free row reads
    __shared__ float colsum[32];
    __shared__ float ctx[32];
    __shared__ float score[N_];

    const int g = blockIdx.x, t = threadIdx.x;
    const float* X = emb + (size_t)g * N_ * 32;
    for (int i = t; i < N_ * 32; i += 256)
        xs[(i >> 5) * 33 + (i & 31)] = X[i];
    __syncthreads();

    if (t < 32) {
        float s = 0.f;
        for (int n = 0; n < N_; n++) s += xs[n * 33 + t];
        colsum[t] = s;
    }
    __syncthreads();
    if (t < 32) {
        float a = 0.f;
        for (int i = 0; i < 32; i++) a += colsum[i] * Watt[t * 32 + i];
        ctx[t] = tanhf(a * (1.0f / 256.0f));
    }
    __syncthreads();
    {
        float d = 0.f;
#pragma unroll
        for (int i = 0; i < 32; i++) d += xs[t * 33 + i] * ctx[i];
        score[t] = 1.0f / (1.0f + expf(-d));
    }
    __syncthreads();
    if (t < 32) {
        float s = 0.f;
        for (int n = 0; n < N_; n++) s += xs[n * 33 + t] * score[n];
        g_pool[g * 32 + t] = s;
    }
}

// ---------------- NTN: relu(e1^T W_t e2 + V_t . [e1;e2] + b_t) ----------------
__global__ void __launch_bounds__(512) k_ntn(const float* __restrict__ ntnW,
                                             const float* __restrict__ ntnV,
                                             const float* __restrict__ ntnb) {
    const int b = blockIdx.x;
    __shared__ float e1[32], e2[32];
    const int t = threadIdx.x;
    if (t < 32)      e1[t]      = g_pool[b * 32 + t];
    else if (t < 64) e2[t - 32] = g_pool[(B_ + b) * 32 + (t - 32)];
    __syncthreads();

    const int w = t >> 5, lane = t & 31;   // w = tensor neuron
    const float* Wt = ntnW + w * 1024;
    float a = 0.f;
#pragma unroll 8
    for (int j = 0; j < 32; j++) a += Wt[lane * 32 + j] * e2[j];
    float partial = e1[lane] * a
                  + e1[lane] * ntnV[w * 64 + lane]
                  + e2[lane] * ntnV[w * 64 + 32 + lane];
#pragma unroll
    for (int o = 16; o; o >>= 1)
        partial += __shfl_xor_sync(0xffffffffu, partial, o);
    if (lane == 0)
        g_scoresT[b * 16 + w] = fmaxf(partial + ntnb[w], 0.f);
}

// ---------------- pairwise dot s[b,n,m] = q_n . c_m, plus global min/max ----------------
__global__ void __launch_bounds__(256) k_pair(const float* __restrict__ emb,
                                              float* __restrict__ s) {
    __shared__ float qs[64 * 32];
    __shared__ float cs[256 * 33];
    __shared__ float wmn[8], wmx[8];

    const int b = blockIdx.y, nt = blockIdx.x;
    const int t = threadIdx.x;
    const float* Q = emb + (size_t)b * N_ * 32 + (size_t)nt * 64 * 32;
    const float* C = emb + (size_t)(B_ + b) * N_ * 32;
    for (int i = t; i < 64 * 32; i += 256) qs[i] = Q[i];
    for (int i = t; i < 256 * 32; i += 256)
        cs[(i >> 5) * 33 + (i & 31)] = C[i];
    __syncthreads();

    float cr[32];
#pragma unroll
    for (int k = 0; k < 32; k++) cr[k] = cs[t * 33 + k];

    float vmin = 3.402823466e38f, vmax = -3.402823466e38f;
    float* Sb = s + (size_t)b * N_ * N_ + (size_t)nt * 64 * N_;
    for (int n = 0; n < 64; n += 4) {
        float a0 = 0.f, a1 = 0.f, a2 = 0.f, a3 = 0.f;
#pragma unroll
        for (int k = 0; k < 32; k++) {
            float cv = cr[k];
            a0 += qs[(n + 0) * 32 + k] * cv;
            a1 += qs[(n + 1) * 32 + k] * cv;
            a2 += qs[(n + 2) * 32 + k] * cv;
            a3 += qs[(n + 3) * 32 + k] * cv;
        }
        Sb[(n + 0) * N_ + t] = a0;
        Sb[(n + 1) * N_ + t] = a1;
        Sb[(n + 2) * N_ + t] = a2;
        Sb[(n + 3) * N_ + t] = a3;
        vmin = fminf(fminf(vmin, a0), fminf(fminf(a1, a2), a3));
        vmax = fmaxf(fmaxf(vmax, a0), fmaxf(fmaxf(a1, a2), a3));
    }
#pragma unroll
    for (int o = 16; o; o >>= 1) {
        vmin = fminf(vmin, __shfl_xor_sync(0xffffffffu, vmin, o));
        vmax = fmaxf(vmax, __shfl_xor_sync(0xffffffffu, vmax, o));
    }
    if ((t & 31) == 0) { wmn[t >> 5] = vmin; wmx[t >> 5] = vmax; }
    __syncthreads();
    if (t == 0) {
        float m = wmn[0], M = wmx[0];
        for (int i = 1; i < 8; i++) { m = fminf(m, wmn[i]); M = fmaxf(M, wmx[i]); }
        atomicMin(&g_minmax[0], encf(m));
        atomicMax(&g_minmax[1], encf(M));
    }
}

// ---------------- histogram over 8.4M values, float4 loads + ballot counting ----------------
__global__ void __launch_bounds__(256) k_hist(const float* __restrict__ s) {
    __shared__ int hsm[16];
    const int t = threadIdx.x;
    if (t < 16) hsm[t] = 0;
    __syncthreads();

    const float lo = decf(g_minmax[0]);
    const float inv = 16.0f / (decf(g_minmax[1]) - lo);
    const int lane = t & 31;
    int cnt = 0;   // lane i accumulates bin i (lanes 16..31 idle)

    const float4* s4 = (const float4*)s;
    // 2097152 float4 total = 1024 blocks * 256 thr * 8 iters
    size_t idx0 = (size_t)blockIdx.x * 256 + t;
    for (int it = 0; it < 8; it++) {
        float4 v = s4[idx0 + (size_t)it * 262144];
        float vv[4] = {v.x, v.y, v.z, v.w};
#pragma unroll
        for (int j = 0; j < 4; j++) {
            int bi = (int)floorf((vv[j] - lo) * inv);
            bi = bi < 0 ? 0 : (bi > 15 ? 15 : bi);
#pragma unroll
            for (int b = 0; b < 16; b++) {
                unsigned m = __ballot_sync(0xffffffffu, bi == b);
                if (lane == b) cnt += __popc(m);
            }
        }
    }
    if (lane < 16) atomicAdd(&hsm[lane], cnt);
    __syncthreads();
    if (t < 16) atomicAdd(&g_hist[t], hsm[t]);
}

// ---------------- final MLP head ----------------
__global__ void k_final(const float* __restrict__ fc1W, const float* __restrict__ fc1b,
                        const float* __restrict__ fc2W, const float* __restrict__ fc2b,
                        float* __restrict__ out) {
    __shared__ float h[16];
    const int b = threadIdx.x;
    if (b < 16) h[b] = (float)g_hist[b] * (1.0f / 8388608.0f);
    __syncthreads();

    float sc[16];
#pragma unroll
    for (int t = 0; t < 16; t++) sc[t] = g_scoresT[b * 16 + t];

    float p = fc2b[0];
#pragma unroll
    for (int j = 0; j < 16; j++) {
        float a = fc1b[j];
#pragma unroll
        for (int t = 0; t < 16; t++) a += sc[t] * fc1W[j * 32 + t];
#pragma unroll
        for (int k = 0; k < 16; k++) a += h[k] * fc1W[j * 32 + 16 + k];
        p += fmaxf(a, 0.f) * fc2W[j];
    }
    out[b] = 1.0f / (1.0f + expf(-p));
}

// ---------------- launch ----------------
extern "C" void kernel_launch(void* const* d_in, const int* in_sizes, int n_in,
                              void* d_out, int out_size) {
    const float* xq   = (const float*)d_in[0];
    const float* xc   = (const float*)d_in[1];
    const int*   eq   = (const int*)d_in[2];
    const int*   ec   = (const int*)d_in[3];
    const float* W1   = (const float*)d_in[4];
    const float* b1   = (const float*)d_in[5];
    const float* W2   = (const float*)d_in[6];
    const float* b2   = (const float*)d_in[7];
    const float* W3   = (const float*)d_in[8];
    const float* b3   = (const float*)d_in[9];
    const float* Watt = (const float*)d_in[10];
    const float* ntnW = (const float*)d_in[11];
    const float* ntnV = (const float*)d_in[12];
    const float* ntnb = (const float*)d_in[13];
    const float* fc1W = (const float*)d_in[14];
    const float* fc1b = (const float*)d_in[15];
    const float* fc2W = (const float*)d_in[16];
    const float* fc2b = (const float*)d_in[17];
    float* out = (float*)d_out;

    float *bufA, *bufB;
    cudaGetSymbolAddress((void**)&bufA, g_bufA);
    cudaGetSymbolAddress((void**)&bufB, g_bufB);

    constexpr int SM_G1 = (128 * 128 + 64 * 128) * 4;       // 96 KB
    constexpr int SM_G2 = (128 * 64  + 64 * 128) * 4;       // 64 KB
    constexpr int SM_G3 = (64 * 32   + 64 * 64)  * 4;       // 24 KB
    constexpr int SM_A1 = (N_ * 128 + 2 * E_ + 260) * 4;    // ~145 KB
    constexpr int SM_A2 = (N_ * 64  + 2 * E_ + 260) * 4;    // ~81 KB
    constexpr int SM_A3 = (N_ * 32  + 2 * E_ + 260) * 4;    // ~49 KB

    cudaFuncSetAttribute(k_gemm<128, 128, true>,  cudaFuncAttributeMaxDynamicSharedMemorySize, SM_G1);
    cudaFuncSetAttribute(k_gemm<128, 64,  false>, cudaFuncAttributeMaxDynamicSharedMemorySize, SM_G2);
    cudaFuncSetAttribute(k_gemm<64,  32,  false>, cudaFuncAttributeMaxDynamicSharedMemorySize, SM_G3);
    cudaFuncSetAttribute(k_agg<128, true>,  cudaFuncAttributeMaxDynamicSharedMemorySize, SM_A1);
    cudaFuncSetAttribute(k_agg<64,  true>,  cudaFuncAttributeMaxDynamicSharedMemorySize, SM_A2);
    cudaFuncSetAttribute(k_agg<32,  false>, cudaFuncAttributeMaxDynamicSharedMemorySize, SM_A3);

    k_csr<<<GTOT, 256>>>(eq, ec);

    k_gemm<128, 128, true><<<dim3(4, GTOT), 256, SM_G1>>>(xq, xc, W1, bufA);
    k_agg<128, true><<<GTOT, 1024, SM_A1>>>(bufA, b1, bufB);

    k_gemm<128, 64, false><<<dim3(4, GTOT), 256, SM_G2>>>(bufB, bufB, W2, bufA);
    k_agg<64, true><<<GTOT, 1024, SM_A2>>>(bufA, b2, bufB);

    k_gemm<64, 32, false><<<dim3(4, GTOT), 256, SM_G3>>>(bufB, bufB, W3, bufA);
    k_agg<32, false><<<GTOT, 1024, SM_A3>>>(bufA, b3, bufB);   // bufB = final node embeddings

    k_pool<<<GTOT, 256>>>(bufB, Watt);
    k_ntn<<<B_, 512>>>(ntnW, ntnV, ntnb);

    k_pair<<<dim3(4, B_), 256>>>(bufB, bufA);   // bufA reused as s [128,256,256]
    k_hist<<<1024, 256>>>(bufA);

    k_final<<<1, B_>>>(fc1W, fc1b, fc2W, fc2b, out);
}

// round 5
// speedup vs baseline: 1.2827x; 1.0403x over previous
#include <cuda_runtime.h>
#include <cuda_bf16.h>
#include <mma.h>
#include <cstdint>
#include <math.h>

using namespace nvcuda;

#define B_   128
#define N_   256
#define E_   2048
#define GTOT 256   // q graphs [0,128) + c graphs [128,256)

// ---------------- device scratch (static globals: no allocs) ----------------
__device__ float    g_bufA[GTOT * N_ * 128];   // 33.5 MB ping (also reused as s)
__device__ float    g_bufB[GTOT * N_ * 128];   // 33.5 MB pong
__device__ float2   g_edge[GTOT * E_];         // packed (coef, src-as-float-bits)
__device__ int      g_rowptr[GTOT * 257];
__device__ float    g_invdeg[GTOT * N_];
__device__ float    g_pool[GTOT * 32];
__device__ float    g_scoresT[B_ * 16];
__device__ unsigned g_minmax[2];
__device__ int      g_hist[16];

// monotone float<->uint mapping for atomicMin/Max over signed floats
__device__ __forceinline__ unsigned encf(float f) {
    unsigned u = __float_as_uint(f);
    return (u & 0x80000000u) ? ~u : (u | 0x80000000u);
}
__device__ __forceinline__ float decf(unsigned u) {
    return (u & 0x80000000u) ? __uint_as_float(u & 0x7fffffffu)
                             : __uint_as_float(~u);
}

// ---------------- CSR build (per graph) + global init in block 0 ----------------
__global__ void __launch_bounds__(256) k_csr(const int* __restrict__ eq,
                                             const int* __restrict__ ec) {
    const int g = blockIdx.x;
    const int t = threadIdx.x;
    if (g == 0) {
        if (t == 0) { g_minmax[0] = 0xffffffffu; g_minmax[1] = 0u; }
        if (t < 16) g_hist[t] = 0;
    }
    const int* base = (g < B_) ? (eq + (size_t)g * 2 * E_)
                               : (ec + (size_t)(g - B_) * 2 * E_);
    const int* src = base;
    const int* dst = base + E_;

    __shared__ int   cnt[256];
    __shared__ int   scan[256];
    __shared__ int   off[256];
    __shared__ float dinv[256];

    cnt[t] = 0;
    __syncthreads();
    for (int e = t; e < E_; e += 256) atomicAdd(&cnt[dst[e]], 1);
    __syncthreads();

    float deg = (float)cnt[t] + 1.0f;
    dinv[t] = rsqrtf(deg);
    g_invdeg[g * N_ + t] = 1.0f / deg;

    int v = cnt[t];
    scan[t] = v;
    __syncthreads();
    for (int s = 1; s < 256; s <<= 1) {
        int add = (t >= s) ? scan[t - s] : 0;
        __syncthreads();
        scan[t] += add;
        __syncthreads();
    }
    int excl = scan[t] - v;
    off[t] = excl;
    g_rowptr[g * 257 + t] = excl;
    if (t == 0) g_rowptr[g * 257 + 256] = E_;
    __syncthreads();

    for (int e = t; e < E_; e += 256) {
        int d = dst[e];
        int s_ = src[e];
        int pos = atomicAdd(&off[d], 1);
        g_edge[g * E_ + pos] = make_float2(dinv[s_] * dinv[d], __int_as_float(s_));
    }
}

// ---------------- wmma split-bf16 GEMM: out[65536,FO] = X[65536,K] @ W[K,FO] ----------------
// D = Ahi*Bhi + Ahi*Blo + Alo*Bhi  (fp32 accumulators; missing lolo ~2^-18 rel)
template<int K, int FO, bool L1>
__global__ void __launch_bounds__(256) k_gemm_tc(const float* __restrict__ inA,
                                                 const float* __restrict__ inB,
                                                 const float* __restrict__ W,
                                                 float* __restrict__ out) {
    constexpr int LDA = K + 8;    // bf16 elems, padded vs bank conflicts
    constexpr int LDB = FO + 8;
    extern __shared__ __align__(16) __nv_bfloat16 sm[];
    __nv_bfloat16* Ahi = sm;                       // 128*LDA
    __nv_bfloat16* Alo = Ahi + 128 * LDA;
    __nv_bfloat16* Bhi = Alo + 128 * LDA;          // K*LDB
    __nv_bfloat16* Blo = Bhi + K * LDB;

    const int t = threadIdx.x, wid = t >> 5;
    const int r0 = blockIdx.x * 128;

    const float* X;
    if constexpr (L1) {
        int g = r0 >> 8, rin = r0 & 255;
        X = (g < B_) ? inA + ((size_t)g * N_ + rin) * K
                     : inB + ((size_t)(g - B_) * N_ + rin) * K;
    } else {
        X = inA + (size_t)r0 * K;
    }

    for (int i = t; i < 128 * K; i += 256) {
        float x = X[i];
        __nv_bfloat16 h = __float2bfloat16(x);
        int r = i / K, c = i % K;
        Ahi[r * LDA + c] = h;
        Alo[r * LDA + c] = __float2bfloat16(x - __bfloat162float(h));
    }
    for (int i = t; i < K * FO; i += 256) {
        float w = W[i];
        __nv_bfloat16 h = __float2bfloat16(w);
        int r = i / FO, c = i % FO;
        Bhi[r * LDB + c] = h;
        Blo[r * LDB + c] = __float2bfloat16(w - __bfloat162float(h));
    }
    __syncthreads();

    constexpr int NT = FO / 16;
    wmma::fragment<wmma::accumulator, 16, 16, 16, float> C[NT];
#pragma unroll
    for (int n = 0; n < NT; n++) wmma::fill_fragment(C[n], 0.0f);

    const __nv_bfloat16* Ah = Ahi + (size_t)(wid * 16) * LDA;
    const __nv_bfloat16* Al = Alo + (size_t)(wid * 16) * LDA;

    for (int k0 = 0; k0 < K; k0 += 16) {
        wmma::fragment<wmma::matrix_a, 16, 16, 16, __nv_bfloat16, wmma::row_major> ah, al;
        wmma::load_matrix_sync(ah, Ah + k0, LDA);
        wmma::load_matrix_sync(al, Al + k0, LDA);
#pragma unroll
        for (int n = 0; n < NT; n++) {
            wmma::fragment<wmma::matrix_b, 16, 16, 16, __nv_bfloat16, wmma::row_major> bh, bl;
            wmma::load_matrix_sync(bh, Bhi + (size_t)k0 * LDB + n * 16, LDB);
            wmma::load_matrix_sync(bl, Blo + (size_t)k0 * LDB + n * 16, LDB);
            wmma::mma_sync(C[n], ah, bh, C[n]);
            wmma::mma_sync(C[n], ah, bl, C[n]);
            wmma::mma_sync(C[n], al, bh, C[n]);
        }
    }

    float* O = out + (size_t)(r0 + wid * 16) * FO;
#pragma unroll
    for (int n = 0; n < NT; n++)
        wmma::store_matrix_sync(O + n * 16, C[n], FO, wmma::mem_row_major);
}

// ---------------- GCN aggregate (float4-vectorized): out = agg + h/deg + b ----------------
template<int FD, bool RELU>
__global__ void __launch_bounds__(1024) k_agg(const float* __restrict__ H,
                                              const float* __restrict__ bias,
                                              float* __restrict__ out) {
    constexpr int QPN = FD / 4;          // feature quads per node
    constexpr int NPB = 1024 / QPN;      // nodes processed concurrently
    extern __shared__ float smf[];
    float4* hsm = (float4*)smf;                       // N_*QPN float4
    float2* esm = (float2*)(smf + N_ * FD);           // E_ float2
    int*    rsm = (int*)(smf + N_ * FD + 2 * E_);     // 257

    const int g = blockIdx.x;
    const int t = threadIdx.x;

    const float4* Hg = (const float4*)(H + (size_t)g * N_ * FD);
    for (int i = t; i < N_ * QPN; i += 1024) hsm[i] = Hg[i];
    {
        const float2* Eg = g_edge + (size_t)g * E_;
        for (int i = t; i < E_; i += 1024) esm[i] = Eg[i];
    }
    for (int i = t; i < 257; i += 1024) rsm[i] = g_rowptr[g * 257 + i];
    __syncthreads();

    const int fq = t % QPN;
    const int n0 = t / QPN;
    const float4 bf = ((const float4*)bias)[fq];
    float4* O = (float4*)(out + (size_t)g * N_ * FD);

#pragma unroll
    for (int n = n0; n < N_; n += NPB) {
        const int e0 = rsm[n], e1 = rsm[n + 1];
        float4 a0 = make_float4(0.f, 0.f, 0.f, 0.f);
        float4 a1 = make_float4(0.f, 0.f, 0.f, 0.f);
        int e = e0;
        for (; e + 1 < e1; e += 2) {
            float2 ed0 = esm[e];
            float2 ed1 = esm[e + 1];
            float4 h0 = hsm[__float_as_int(ed0.y) * QPN + fq];
            float4 h1 = hsm[__float_as_int(ed1.y) * QPN + fq];
            a0.x += h0.x * ed0.x; a0.y += h0.y * ed0.x;
            a0.z += h0.z * ed0.x; a0.w += h0.w * ed0.x;
            a1.x += h1.x * ed1.x; a1.y += h1.y * ed1.x;
            a1.z += h1.z * ed1.x; a1.w += h1.w * ed1.x;
        }
        if (e < e1) {
            float2 ed0 = esm[e];
            float4 h0 = hsm[__float_as_int(ed0.y) * QPN + fq];
            a0.x += h0.x * ed0.x; a0.y += h0.y * ed0.x;
            a0.z += h0.z * ed0.x; a0.w += h0.w * ed0.x;
        }
        const float id = g_invdeg[g * N_ + n];
        float4 hs = hsm[n * QPN + fq];
        float4 v;
        v.x = a0.x + a1.x + hs.x * id + bf.x;
        v.y = a0.y + a1.y + hs.y * id + bf.y;
        v.z = a0.z + a1.z + hs.z * id + bf.z;
        v.w = a0.w + a1.w + hs.w * id + bf.w;
        if (RELU) {
            v.x = fmaxf(v.x, 0.f); v.y = fmaxf(v.y, 0.f);
            v.z = fmaxf(v.z, 0.f); v.w = fmaxf(v.w, 0.f);
        }
        O[n * QPN + fq] = v;
    }
}

// ---------------- SimGNN attention pooling (f3 = 32) ----------------
__global__ void __launch_bounds__(256) k_pool(const float* __restrict__ emb,
                                              const float* __restrict__ Watt) {
    __shared__ float xs[N_ * 33];   // padded rows: conflict-free row reads
    __shared__ float colsum[32];
    __shared__ float ctx[32];
    __shared__ float score[N_];

    const int g = blockIdx.x, t = threadIdx.x;
    const float* X = emb + (size_t)g * N_ * 32;
    for (int i = t; i < N_ * 32; i += 256)
        xs[(i >> 5) * 33 + (i & 31)] = X[i];
    __syncthreads();

    if (t < 32) {
        float s = 0.f;
        for (int n = 0; n < N_; n++) s += xs[n * 33 + t];
        colsum[t] = s;
    }
    __syncthreads();
    if (t < 32) {
        float a = 0.f;
        for (int i = 0; i < 32; i++) a += colsum[i] * Watt[t * 32 + i];
        ctx[t] = tanhf(a * (1.0f / 256.0f));
    }
    __syncthreads();
    {
        float d = 0.f;
#pragma unroll
        for (int i = 0; i < 32; i++) d += xs[t * 33 + i] * ctx[i];
        score[t] = 1.0f / (1.0f + expf(-d));
    }
    __syncthreads();
    if (t < 32) {
        float s = 0.f;
        for (int n = 0; n < N_; n++) s += xs[n * 33 + t] * score[n];
        g_pool[g * 32 + t] = s;
    }
}

// ---------------- NTN: relu(e1^T W_t e2 + V_t . [e1;e2] + b_t) ----------------
__global__ void __launch_bounds__(512) k_ntn(const float* __restrict__ ntnW,
                                             const float* __restrict__ ntnV,
                                             const float* __restrict__ ntnb) {
    const int b = blockIdx.x;
    __shared__ float e1[32], e2[32];
    const int t = threadIdx.x;
    if (t < 32)      e1[t]      = g_pool[b * 32 + t];
    else if (t < 64) e2[t - 32] = g_pool[(B_ + b) * 32 + (t - 32)];
    __syncthreads();

    const int w = t >> 5, lane = t & 31;   // w = tensor neuron
    const float* Wt = ntnW + w * 1024;
    float a = 0.f;
#pragma unroll 8
    for (int j = 0; j < 32; j++) a += Wt[lane * 32 + j] * e2[j];
    float partial = e1[lane] * a
                  + e1[lane] * ntnV[w * 64 + lane]
                  + e2[lane] * ntnV[w * 64 + 32 + lane];
#pragma unroll
    for (int o = 16; o; o >>= 1)
        partial += __shfl_xor_sync(0xffffffffu, partial, o);
    if (lane == 0)
        g_scoresT[b * 16 + w] = fmaxf(partial + ntnb[w], 0.f);
}

// ---------------- pairwise dot s[b,n,m] = q_n . c_m, plus global min/max ----------------
__global__ void __launch_bounds__(256) k_pair(const float* __restrict__ emb,
                                              float* __restrict__ s) {
    __shared__ float qs[64 * 32];
    __shared__ float cs[256 * 33];
    __shared__ float wmn[8], wmx[8];

    const int b = blockIdx.y, nt = blockIdx.x;
    const int t = threadIdx.x;
    const float* Q = emb + (size_t)b * N_ * 32 + (size_t)nt * 64 * 32;
    const float* C = emb + (size_t)(B_ + b) * N_ * 32;
    for (int i = t; i < 64 * 32; i += 256) qs[i] = Q[i];
    for (int i = t; i < 256 * 32; i += 256)
        cs[(i >> 5) * 33 + (i & 31)] = C[i];
    __syncthreads();

    float cr[32];
#pragma unroll
    for (int k = 0; k < 32; k++) cr[k] = cs[t * 33 + k];

    float vmin = 3.402823466e38f, vmax = -3.402823466e38f;
    float* Sb = s + (size_t)b * N_ * N_ + (size_t)nt * 64 * N_;
    for (int n = 0; n < 64; n += 4) {
        float a0 = 0.f, a1 = 0.f, a2 = 0.f, a3 = 0.f;
#pragma unroll
        for (int k = 0; k < 32; k++) {
            float cv = cr[k];
            a0 += qs[(n + 0) * 32 + k] * cv;
            a1 += qs[(n + 1) * 32 + k] * cv;
            a2 += qs[(n + 2) * 32 + k] * cv;
            a3 += qs[(n + 3) * 32 + k] * cv;
        }
        Sb[(n + 0) * N_ + t] = a0;
        Sb[(n + 1) * N_ + t] = a1;
        Sb[(n + 2) * N_ + t] = a2;
        Sb[(n + 3) * N_ + t] = a3;
        vmin = fminf(fminf(vmin, a0), fminf(fminf(a1, a2), a3));
        vmax = fmaxf(fmaxf(vmax, a0), fmaxf(fmaxf(a1, a2), a3));
    }
#pragma unroll
    for (int o = 16; o; o >>= 1) {
        vmin = fminf(vmin, __shfl_xor_sync(0xffffffffu, vmin, o));
        vmax = fmaxf(vmax, __shfl_xor_sync(0xffffffffu, vmax, o));
    }
    if ((t & 31) == 0) { wmn[t >> 5] = vmin; wmx[t >> 5] = vmax; }
    __syncthreads();
    if (t == 0) {
        float m = wmn[0], M = wmx[0];
        for (int i = 1; i < 8; i++) { m = fminf(m, wmn[i]); M = fmaxf(M, wmx[i]); }
        atomicMin(&g_minmax[0], encf(m));
        atomicMax(&g_minmax[1], encf(M));
    }
}

// ---------------- histogram over 8.4M values, float4 loads + ballot counting ----------------
__global__ void __launch_bounds__(256) k_hist(const float* __restrict__ s) {
    __shared__ int hsm[16];
    const int t = threadIdx.x;
    if (t < 16) hsm[t] = 0;
    __syncthreads();

    const float lo = decf(g_minmax[0]);
    const float inv = 16.0f / (decf(g_minmax[1]) - lo);
    const int lane = t & 31;
    int cnt = 0;   // lane i accumulates bin i (lanes 16..31 idle)

    const float4* s4 = (const float4*)s;
    // 2097152 float4 total = 1024 blocks * 256 thr * 8 iters
    size_t idx0 = (size_t)blockIdx.x * 256 + t;
    for (int it = 0; it < 8; it++) {
        float4 v = s4[idx0 + (size_t)it * 262144];
        float vv[4] = {v.x, v.y, v.z, v.w};
#pragma unroll
        for (int j = 0; j < 4; j++) {
            int bi = (int)floorf((vv[j] - lo) * inv);
            bi = bi < 0 ? 0 : (bi > 15 ? 15 : bi);
#pragma unroll
            for (int b = 0; b < 16; b++) {
                unsigned m = __ballot_sync(0xffffffffu, bi == b);
                if (lane == b) cnt += __popc(m);
            }
        }
    }
    if (lane < 16) atomicAdd(&hsm[lane], cnt);
    __syncthreads();
    if (t < 16) atomicAdd(&g_hist[t], hsm[t]);
}

// ---------------- final MLP head ----------------
__global__ void k_final(const float* __restrict__ fc1W, const float* __restrict__ fc1b,
                        const float* __restrict__ fc2W, const float* __restrict__ fc2b,
                        float* __restrict__ out) {
    __shared__ float h[16];
    const int b = threadIdx.x;
    if (b < 16) h[b] = (float)g_hist[b] * (1.0f / 8388608.0f);
    __syncthreads();

    float sc[16];
#pragma unroll
    for (int t = 0; t < 16; t++) sc[t] = g_scoresT[b * 16 + t];

    float p = fc2b[0];
#pragma unroll
    for (int j = 0; j < 16; j++) {
        float a = fc1b[j];
#pragma unroll
        for (int t = 0; t < 16; t++) a += sc[t] * fc1W[j * 32 + t];
#pragma unroll
        for (int k = 0; k < 16; k++) a += h[k] * fc1W[j * 32 + 16 + k];
        p += fmaxf(a, 0.f) * fc2W[j];
    }
    out[b] = 1.0f / (1.0f + expf(-p));
}

// ---------------- launch ----------------
extern "C" void kernel_launch(void* const* d_in, const int* in_sizes, int n_in,
                              void* d_out, int out_size) {
    const float* xq   = (const float*)d_in[0];
    const float* xc   = (const float*)d_in[1];
    const int*   eq   = (const int*)d_in[2];
    const int*   ec   = (const int*)d_in[3];
    const float* W1   = (const float*)d_in[4];
    const float* b1   = (const float*)d_in[5];
    const float* W2   = (const float*)d_in[6];
    const float* b2   = (const float*)d_in[7];
    const float* W3   = (const float*)d_in[8];
    const float* b3   = (const float*)d_in[9];
    const float* Watt = (const float*)d_in[10];
    const float* ntnW = (const float*)d_in[11];
    const float* ntnV = (const float*)d_in[12];
    const float* ntnb = (const float*)d_in[13];
    const float* fc1W = (const float*)d_in[14];
    const float* fc1b = (const float*)d_in[15];
    const float* fc2W = (const float*)d_in[16];
    const float* fc2b = (const float*)d_in[17];
    float* out = (float*)d_out;

    float *bufA, *bufB;
    cudaGetSymbolAddress((void**)&bufA, g_bufA);
    cudaGetSymbolAddress((void**)&bufB, g_bufB);

    // smem bytes: 2*(128*(K+8)) + 2*(K*(FO+8)) bf16 elems
    constexpr int SM_T1 = (2 * 128 * 136 + 2 * 128 * 136) * 2;   // 139264
    constexpr int SM_T2 = (2 * 128 * 136 + 2 * 128 * 72)  * 2;   // 106496
    constexpr int SM_T3 = (2 * 128 * 72  + 2 * 64 * 40)   * 2;   // 47104
    constexpr int SM_A1 = (N_ * 128 + 2 * E_ + 260) * 4;    // ~145 KB
    constexpr int SM_A2 = (N_ * 64  + 2 * E_ + 260) * 4;    // ~81 KB
    constexpr int SM_A3 = (N_ * 32  + 2 * E_ + 260) * 4;    // ~49 KB

    cudaFuncSetAttribute(k_gemm_tc<128, 128, true>,  cudaFuncAttributeMaxDynamicSharedMemorySize, SM_T1);
    cudaFuncSetAttribute(k_gemm_tc<128, 64,  false>, cudaFuncAttributeMaxDynamicSharedMemorySize, SM_T2);
    cudaFuncSetAttribute(k_gemm_tc<64,  32,  false>, cudaFuncAttributeMaxDynamicSharedMemorySize, SM_T3);
    cudaFuncSetAttribute(k_agg<128, true>,  cudaFuncAttributeMaxDynamicSharedMemorySize, SM_A1);
    cudaFuncSetAttribute(k_agg<64,  true>,  cudaFuncAttributeMaxDynamicSharedMemorySize, SM_A2);
    cudaFuncSetAttribute(k_agg<32,  false>, cudaFuncAttributeMaxDynamicSharedMemorySize, SM_A3);

    k_csr<<<GTOT, 256>>>(eq, ec);

    k_gemm_tc<128, 128, true><<<512, 256, SM_T1>>>(xq, xc, W1, bufA);
    k_agg<128, true><<<GTOT, 1024, SM_A1>>>(bufA, b1, bufB);

    k_gemm_tc<128, 64, false><<<512, 256, SM_T2>>>(bufB, bufB, W2, bufA);
    k_agg<64, true><<<GTOT, 1024, SM_A2>>>(bufA, b2, bufB);

    k_gemm_tc<64, 32, false><<<512, 256, SM_T3>>>(bufB, bufB, W3, bufA);
    k_agg<32, false><<<GTOT, 1024, SM_A3>>>(bufA, b3, bufB);   // bufB = final node embeddings

    k_pool<<<GTOT, 256>>>(bufB, Watt);
    k_ntn<<<B_, 512>>>(ntnW, ntnV, ntnb);

    k_pair<<<dim3(4, B_), 256>>>(bufB, bufA);   // bufA reused as s [128,256,256]
    k_hist<<<1024, 256>>>(bufA);

    k_final<<<1, B_>>>(fc1W, fc1b, fc2W, fc2b, out);
}